// round 15
// baseline (speedup 1.0000x reference)
#include <cuda_runtime.h>
#include <cuda_fp16.h>
#include <cstdint>

#define C_DIM   128
#define N_COMP  16
#define BM      128
#define THREADS 640   // warps 0-15 consumers, 16-19 producers
#define NBUF    5

// smem (192KB): X ring: 5 x 32KB fp16 tiles @ p*32768; W @ 163840 (32KB)
#define XBUF(p)  ((uint32_t)(p) << 15)
#define OFF_W    163840u
#define HALF     16384u   // one k-half of a 128-row fp16 tile (128 rows * 128B)

__device__ __forceinline__ uint32_t smem_u32(const void* p) {
    uint32_t a;
    asm("{ .reg .u64 t; cvta.to.shared.u64 t, %1; cvt.u32.u64 %0, t; }"
        : "=r"(a) : "l"(p));
    return a;
}
__device__ __forceinline__ void bar_sync(int id) {
    asm volatile("bar.sync %0, %1;" :: "r"(id), "r"(THREADS) : "memory");
}
__device__ __forceinline__ void bar_arrive(int id) {
    asm volatile("bar.arrive %0, %1;" :: "r"(id), "r"(THREADS) : "memory");
}
__device__ __forceinline__ void ldmx4(uint32_t& r0, uint32_t& r1,
                                      uint32_t& r2, uint32_t& r3, uint32_t addr) {
    asm volatile("ldmatrix.sync.aligned.m8n8.x4.shared.b16 {%0,%1,%2,%3}, [%4];"
                 : "=r"(r0), "=r"(r1), "=r"(r2), "=r"(r3) : "r"(addr));
}
__device__ __forceinline__ void mma_f16(float* c, const uint32_t* a,
                                        uint32_t b0, uint32_t b1) {
    asm volatile(
        "mma.sync.aligned.m16n8k16.row.col.f32.f16.f16.f32 "
        "{%0,%1,%2,%3}, {%4,%5,%6,%7}, {%8,%9}, {%0,%1,%2,%3};"
        : "+f"(c[0]), "+f"(c[1]), "+f"(c[2]), "+f"(c[3])
        : "r"(a[0]), "r"(a[1]), "r"(a[2]), "r"(a[3]), "r"(b0), "r"(b1));
}

// swizzled byte offset within a 128row x 128k fp16 tile: two 16KB k-halves
// (64 k each, 128B rows), 16B chunks XOR-permuted by row&7
__device__ __forceinline__ uint32_t swz_off(int row, int k) {
    return ((uint32_t)(k >> 6) << 14) + ((uint32_t)row << 7)
         + ((uint32_t)((((k & 63) >> 3) ^ (row & 7))) << 4)
         + (uint32_t)((k & 7) << 1);
}

// exact magic division by cl = 2l+1
__device__ __forceinline__ uint32_t div_cl(uint32_t r, uint64_t M, int S) {
    return (uint32_t)(((uint64_t)r * M) >> S);
}

// Warp-specialized persistent single-pass fp16 kernel, 5-deep X ring.
// 640 threads: reg cap 102 gives ptxas fragment-pipelining headroom.
__global__ __launch_bounds__(THREADS, 1)
void tp_f16d(const float* __restrict__ x,
             const float* __restrict__ w,
             const float* __restrict__ pw,
             float* __restrict__ out,
             int n_nodes, int4 cum)
{
    extern __shared__ __align__(128) char smem[];
    const uint32_t sb = smem_u32(smem);

    const int tid  = threadIdx.x;
    const int lane = tid & 31;
    const int warp = tid >> 5;

    const int T  = cum.w;
    const int t0 = (int)(((long long)blockIdx.x * T) / gridDim.x);
    const int t1 = (int)(((long long)(blockIdx.x + 1) * T) / gridDim.x);
    if (t0 >= t1) return;

    auto l_of = [&](int g) {
        return (g < cum.x) ? 0 : (g < cum.y) ? 1 : (g < cum.z) ? 2 : 3;
    };
    const int l_first = l_of(t0);
    const int l_last  = l_of(t1 - 1);

    // consumer lane decomposition (32x32 warp tile)
    const int wr = warp & 3;
    const int wc = warp >> 2;
    const int a_hi = lane >> 4;
    int a_row[2], a_s[2];
    #pragma unroll
    for (int mt = 0; mt < 2; mt++) {
        a_row[mt] = wr * 32 + mt * 16 + (lane & 15);
        a_s[mt]   = a_row[mt] & 7;
    }
    const int bg   = lane >> 3;
    const int b_hi = bg & 1;
    int b_row[2], b_s[2];
    #pragma unroll
    for (int nt = 0; nt < 2; nt++) {
        b_row[nt] = wc * 32 + nt * 16 + ((bg >> 1) * 8) + (lane & 7);
        b_s[nt]   = b_row[nt] & 7;
    }
    const int grp = lane >> 2;
    const int qid = lane & 3;

    // producer decomposition: 4 warps = 128 threads; each wave covers 64 rows
    const int ptid   = tid - 512;
    const int my_lr4 = ptid >> 5;    // 0..3 (row within 4-row chunk)
    const int my_v   = ptid & 31;    // float4 column
    const float4* x4 = (const float4*)x;

    for (int l = l_first; l <= l_last; l++) {
        const int cp = (l == 0) ? 0 : (l == 1) ? cum.x : (l == 2) ? cum.y : cum.z;
        const int ce = (l == 0) ? cum.x : (l == 1) ? cum.y : (l == 2) ? cum.z : cum.w;
        int s0 = t0 > cp ? t0 : cp;
        int s1 = t1 < ce ? t1 : ce;
        if (s0 >= s1) continue;
        const int n = s1 - s0;

        const int cl     = 2 * l + 1;
        const int mbase  = l * l;
        const int rows_l = n_nodes * cl;
        const uint64_t M = (l == 0) ? 1ull : (l == 1) ? 0xAAAAAAABull
                         : (l == 2) ? 0xCCCCCCCDull : 0x92492493ull;
        const int S = (l == 0) ? 0 : (l == 1) ? 33 : 34;

        // ---- stage W[l]*pw -> fp16 [n][k] swizzled (all threads) ----
        __syncthreads();
        {
            const float scale = __ldg(&pw[l]);
            const float* wp = w + (size_t)l * C_DIM * C_DIM;
            #pragma unroll
            for (int e = tid; e < C_DIM * C_DIM; e += THREADS) {
                int k = e >> 7, nn = e & 127;
                __half h = __float2half_rn(wp[e] * scale);
                *(__half*)(smem + OFF_W + swz_off(nn, k)) = h;
            }
        }
        __syncthreads();

        if (warp >= 16) {
            // ================= PRODUCER (4 warps, 2 waves of 16 LDG) =========
            int p = 0;
            for (int i = 0; i < n; i++) {
                const int row0 = (s0 + i - cp) * BM;
                const uint32_t xb = XBUF(p);
                #pragma unroll
                for (int wave = 0; wave < 2; wave++) {
                    float4 v[16];
                    #pragma unroll
                    for (int c = 0; c < 16; c++) {
                        int lr = wave * 64 + c * 4 + my_lr4;
                        int r  = row0 + lr;
                        v[c] = make_float4(0.f, 0.f, 0.f, 0.f);
                        if (r < rows_l) {
                            uint32_t node = div_cl((uint32_t)r, M, S);
                            uint32_t m    = (uint32_t)mbase + ((uint32_t)r - node * cl);
                            v[c] = __ldg(x4 + ((size_t)node * N_COMP + m) * 32 + my_v);
                        }
                    }
                    if (wave == 0 && i >= NBUF) bar_sync(8 + p);
                    #pragma unroll
                    for (int c = 0; c < 16; c++) {
                        int lr = wave * 64 + c * 4 + my_lr4;
                        uint2 u;
                        __half2 h0 = __floats2half2_rn(v[c].x, v[c].y);
                        __half2 h1 = __floats2half2_rn(v[c].z, v[c].w);
                        u.x = *(uint32_t*)&h0;
                        u.y = *(uint32_t*)&h1;
                        *(uint2*)(smem + xb + swz_off(lr, my_v * 4)) = u;
                    }
                }
                bar_arrive(1 + p);
                if (++p == NBUF) p = 0;
            }
        } else {
            // ================= CONSUMER =================
            int p = 0;
            for (int i = 0; i < n; i++) {
                const int row0 = (s0 + i - cp) * BM;
                const uint32_t xb = sb + XBUF(p);

                bar_sync(1 + p);

                float acc[2][4][4];
                #pragma unroll
                for (int mt = 0; mt < 2; mt++)
                    #pragma unroll
                    for (int n8 = 0; n8 < 4; n8++)
                        #pragma unroll
                        for (int j = 0; j < 4; j++) acc[mt][n8][j] = 0.f;

                #pragma unroll
                for (int ks = 0; ks < 8; ks++) {
                    const uint32_t hoff = (ks & 4) ? HALF : 0u;
                    const int c0 = (ks & 3) * 2;

                    uint32_t A[2][4];
                    #pragma unroll
                    for (int mt = 0; mt < 2; mt++) {
                        uint32_t a = xb + hoff + (uint32_t)(a_row[mt] << 7)
                                   + (uint32_t)((((c0 | a_hi) ^ a_s[mt])) << 4);
                        ldmx4(A[mt][0], A[mt][1], A[mt][2], A[mt][3], a);
                    }
                    uint32_t B[2][4];
                    #pragma unroll
                    for (int nt = 0; nt < 2; nt++) {
                        uint32_t b = sb + OFF_W + hoff
                                   + (uint32_t)(b_row[nt] << 7)
                                   + (uint32_t)((((c0 | b_hi) ^ b_s[nt])) << 4);
                        ldmx4(B[nt][0], B[nt][1], B[nt][2], B[nt][3], b);
                    }
                    #pragma unroll
                    for (int mt = 0; mt < 2; mt++)
                        #pragma unroll
                        for (int n8 = 0; n8 < 4; n8++) {
                            const int nt = n8 >> 1, q = (n8 & 1) * 2;
                            mma_f16(acc[mt][n8], A[mt], B[nt][q], B[nt][q + 1]);
                        }
                }

                // free buffer p (skip last NBUF tiles to keep barriers drained)
                if (i + NBUF + 1 <= n) bar_arrive(8 + p);

                // ---- epilogue ----
                #pragma unroll
                for (int mt = 0; mt < 2; mt++) {
                    #pragma unroll
                    for (int h = 0; h < 2; h++) {
                        int r = row0 + wr * 32 + mt * 16 + grp + h * 8;
                        if (r < rows_l) {
                            uint32_t node = div_cl((uint32_t)r, M, S);
                            uint32_t m    = (uint32_t)mbase + ((uint32_t)r - node * cl);
                            float* orow = out + ((size_t)node * N_COMP + m) * C_DIM
                                              + wc * 32 + qid * 2;
                            #pragma unroll
                            for (int n8 = 0; n8 < 4; n8++) {
                                float2 v2 = make_float2(acc[mt][n8][h * 2],
                                                        acc[mt][n8][h * 2 + 1]);
                                *(float2*)(orow + n8 * 8) = v2;
                            }
                        }
                    }
                }
                if (++p == NBUF) p = 0;
            }
        }
    }
}

extern "C" void kernel_launch(void* const* d_in, const int* in_sizes, int n_in,
                              void* d_out, int out_size) {
    const float* x  = (const float*)d_in[0];
    const float* w  = (const float*)d_in[1];
    const float* pw = (const float*)d_in[2];
    float* out = (float*)d_out;

    const int n_nodes = in_sizes[0] / (N_COMP * C_DIM);

    int dev = 0, nsm = 148;
    cudaGetDevice(&dev);
    cudaDeviceGetAttribute(&nsm, cudaDevAttrMultiProcessorCount, dev);

    int t[4];
    int4 cum;
    for (int l = 0; l < 4; l++)
        t[l] = (n_nodes * (2 * l + 1) + BM - 1) / BM;
    cum.x = t[0];
    cum.y = cum.x + t[1];
    cum.z = cum.y + t[2];
    cum.w = cum.z + t[3];

    size_t smem_bytes = 196608;   // 192KB: 5x32KB X ring + 32KB W
    cudaFuncSetAttribute(tp_f16d,
                         cudaFuncAttributeMaxDynamicSharedMemorySize,
                         (int)smem_bytes);

    tp_f16d<<<nsm, THREADS, smem_bytes>>>(x, w, pw, out, n_nodes, cum);
}

// round 16
// speedup vs baseline: 1.3602x; 1.3602x over previous
#include <cuda_runtime.h>
#include <cuda_fp16.h>
#include <cstdint>

#define C_DIM   128
#define N_COMP  16
#define BM      128
#define THREADS 768   // warps 0-15 consumers, 16-23 producers
#define NBUF    5

// smem (192KB): X ring: 5 x 32KB fp16 tiles @ p*32768; W @ 163840 (32KB)
#define XBUF(p)  ((uint32_t)(p) << 15)
#define OFF_W    163840u
#define HALF     16384u   // one k-half of a 128-row fp16 tile (128 rows * 128B)

__device__ __forceinline__ uint32_t smem_u32(const void* p) {
    uint32_t a;
    asm("{ .reg .u64 t; cvta.to.shared.u64 t, %1; cvt.u32.u64 %0, t; }"
        : "=r"(a) : "l"(p));
    return a;
}
__device__ __forceinline__ void bar_sync(int id) {
    asm volatile("bar.sync %0, %1;" :: "r"(id), "r"(THREADS) : "memory");
}
__device__ __forceinline__ void bar_arrive(int id) {
    asm volatile("bar.arrive %0, %1;" :: "r"(id), "r"(THREADS) : "memory");
}
__device__ __forceinline__ void ldmx4(uint32_t& r0, uint32_t& r1,
                                      uint32_t& r2, uint32_t& r3, uint32_t addr) {
    asm volatile("ldmatrix.sync.aligned.m8n8.x4.shared.b16 {%0,%1,%2,%3}, [%4];"
                 : "=r"(r0), "=r"(r1), "=r"(r2), "=r"(r3) : "r"(addr));
}
__device__ __forceinline__ void mma_f16(float* c, const uint32_t* a,
                                        uint32_t b0, uint32_t b1) {
    asm volatile(
        "mma.sync.aligned.m16n8k16.row.col.f32.f16.f16.f32 "
        "{%0,%1,%2,%3}, {%4,%5,%6,%7}, {%8,%9}, {%0,%1,%2,%3};"
        : "+f"(c[0]), "+f"(c[1]), "+f"(c[2]), "+f"(c[3])
        : "r"(a[0]), "r"(a[1]), "r"(a[2]), "r"(a[3]), "r"(b0), "r"(b1));
}

// swizzled byte offset within a 128row x 128k fp16 tile: two 16KB k-halves
// (64 k each, 128B rows), 16B chunks XOR-permuted by row&7
__device__ __forceinline__ uint32_t swz_off(int row, int k) {
    return ((uint32_t)(k >> 6) << 14) + ((uint32_t)row << 7)
         + ((uint32_t)((((k & 63) >> 3) ^ (row & 7))) << 4)
         + (uint32_t)((k & 7) << 1);
}

// exact magic division by cl = 2l+1
__device__ __forceinline__ uint32_t div_cl(uint32_t r, uint64_t M, int S) {
    return (uint32_t)(((uint64_t)r * M) >> S);
}

// Warp-specialized persistent single-pass fp16 kernel, 5-deep X ring,
// MLP-16 producer, shuffle-coalesced float4 epilogue stores.
__global__ __launch_bounds__(THREADS, 1)
void tp_f16e(const float* __restrict__ x,
             const float* __restrict__ w,
             const float* __restrict__ pw,
             float* __restrict__ out,
             int n_nodes, int4 cum)
{
    extern __shared__ __align__(128) char smem[];
    const uint32_t sb = smem_u32(smem);

    const int tid  = threadIdx.x;
    const int lane = tid & 31;
    const int warp = tid >> 5;

    const int T  = cum.w;
    const int t0 = (int)(((long long)blockIdx.x * T) / gridDim.x);
    const int t1 = (int)(((long long)(blockIdx.x + 1) * T) / gridDim.x);
    if (t0 >= t1) return;

    auto l_of = [&](int g) {
        return (g < cum.x) ? 0 : (g < cum.y) ? 1 : (g < cum.z) ? 2 : 3;
    };
    const int l_first = l_of(t0);
    const int l_last  = l_of(t1 - 1);

    // consumer lane decomposition (32x32 warp tile)
    const int wr = warp & 3;
    const int wc = warp >> 2;
    const int a_hi = lane >> 4;
    int a_row[2], a_s[2];
    #pragma unroll
    for (int mt = 0; mt < 2; mt++) {
        a_row[mt] = wr * 32 + mt * 16 + (lane & 15);
        a_s[mt]   = a_row[mt] & 7;
    }
    const int bg   = lane >> 3;
    const int b_hi = bg & 1;
    int b_row[2], b_s[2];
    #pragma unroll
    for (int nt = 0; nt < 2; nt++) {
        b_row[nt] = wc * 32 + nt * 16 + ((bg >> 1) * 8) + (lane & 7);
        b_s[nt]   = b_row[nt] & 7;
    }
    const int grp = lane >> 2;
    const int qid = lane & 3;
    const bool odd = (qid & 1);

    const int ptid  = tid - 512;
    const int my_lr = ptid >> 5;
    const int my_v  = ptid & 31;
    const float4* x4 = (const float4*)x;

    for (int l = l_first; l <= l_last; l++) {
        const int cp = (l == 0) ? 0 : (l == 1) ? cum.x : (l == 2) ? cum.y : cum.z;
        const int ce = (l == 0) ? cum.x : (l == 1) ? cum.y : (l == 2) ? cum.z : cum.w;
        int s0 = t0 > cp ? t0 : cp;
        int s1 = t1 < ce ? t1 : ce;
        if (s0 >= s1) continue;
        const int n = s1 - s0;

        const int cl     = 2 * l + 1;
        const int mbase  = l * l;
        const int rows_l = n_nodes * cl;
        const uint64_t M = (l == 0) ? 1ull : (l == 1) ? 0xAAAAAAABull
                         : (l == 2) ? 0xCCCCCCCDull : 0x92492493ull;
        const int S = (l == 0) ? 0 : (l == 1) ? 33 : 34;

        // ---- stage W[l]*pw -> fp16 [n][k] swizzled (all threads) ----
        __syncthreads();
        {
            const float scale = __ldg(&pw[l]);
            const float* wp = w + (size_t)l * C_DIM * C_DIM;
            #pragma unroll
            for (int e = tid; e < C_DIM * C_DIM; e += THREADS) {
                int k = e >> 7, nn = e & 127;
                __half h = __float2half_rn(wp[e] * scale);
                *(__half*)(smem + OFF_W + swz_off(nn, k)) = h;
            }
        }
        __syncthreads();

        if (warp >= 16) {
            // ================= PRODUCER (8 warps, MLP=16) =================
            int p = 0;
            for (int i = 0; i < n; i++) {
                const int row0 = (s0 + i - cp) * BM;
                const uint32_t xb = XBUF(p);

                float4 v[16];
                #pragma unroll
                for (int c = 0; c < 16; c++) {
                    int lr = c * 8 + my_lr;
                    int r  = row0 + lr;
                    v[c] = make_float4(0.f, 0.f, 0.f, 0.f);
                    if (r < rows_l) {
                        uint32_t node = div_cl((uint32_t)r, M, S);
                        uint32_t m    = (uint32_t)mbase + ((uint32_t)r - node * cl);
                        v[c] = __ldg(x4 + ((size_t)node * N_COMP + m) * 32 + my_v);
                    }
                }
                if (i >= NBUF) bar_sync(8 + p);
                #pragma unroll
                for (int c = 0; c < 16; c++) {
                    int lr = c * 8 + my_lr;
                    uint2 u;
                    __half2 h0 = __floats2half2_rn(v[c].x, v[c].y);
                    __half2 h1 = __floats2half2_rn(v[c].z, v[c].w);
                    u.x = *(uint32_t*)&h0;
                    u.y = *(uint32_t*)&h1;
                    *(uint2*)(smem + xb + swz_off(lr, my_v * 4)) = u;
                }
                bar_arrive(1 + p);
                if (++p == NBUF) p = 0;
            }
        } else {
            // ================= CONSUMER =================
            int p = 0;
            for (int i = 0; i < n; i++) {
                const int row0 = (s0 + i - cp) * BM;
                const uint32_t xb = sb + XBUF(p);

                bar_sync(1 + p);

                float acc[2][4][4];
                #pragma unroll
                for (int mt = 0; mt < 2; mt++)
                    #pragma unroll
                    for (int n8 = 0; n8 < 4; n8++)
                        #pragma unroll
                        for (int j = 0; j < 4; j++) acc[mt][n8][j] = 0.f;

                #pragma unroll
                for (int ks = 0; ks < 8; ks++) {
                    const uint32_t hoff = (ks & 4) ? HALF : 0u;
                    const int c0 = (ks & 3) * 2;

                    uint32_t A[2][4];
                    #pragma unroll
                    for (int mt = 0; mt < 2; mt++) {
                        uint32_t a = xb + hoff + (uint32_t)(a_row[mt] << 7)
                                   + (uint32_t)((((c0 | a_hi) ^ a_s[mt])) << 4);
                        ldmx4(A[mt][0], A[mt][1], A[mt][2], A[mt][3], a);
                    }
                    uint32_t B[2][4];
                    #pragma unroll
                    for (int nt = 0; nt < 2; nt++) {
                        uint32_t b = sb + OFF_W + hoff
                                   + (uint32_t)(b_row[nt] << 7)
                                   + (uint32_t)((((c0 | b_hi) ^ b_s[nt])) << 4);
                        ldmx4(B[nt][0], B[nt][1], B[nt][2], B[nt][3], b);
                    }
                    #pragma unroll
                    for (int mt = 0; mt < 2; mt++)
                        #pragma unroll
                        for (int n8 = 0; n8 < 4; n8++) {
                            const int nt = n8 >> 1, q = (n8 & 1) * 2;
                            mma_f16(acc[mt][n8], A[mt], B[nt][q], B[nt][q + 1]);
                        }
                }

                // free buffer p (skip last NBUF tiles to keep barriers drained)
                if (i + NBUF + 1 <= n) bar_arrive(8 + p);

                // ---- epilogue: xor-1 shuffle -> contiguous float4 stores ----
                #pragma unroll
                for (int mt = 0; mt < 2; mt++) {
                    #pragma unroll
                    for (int h = 0; h < 2; h++) {
                        int r = row0 + wr * 32 + mt * 16 + grp + h * 8;
                        bool ok = (r < rows_l);
                        float* orow = out;   // computed only if ok
                        if (ok) {
                            uint32_t node = div_cl((uint32_t)r, M, S);
                            uint32_t m    = (uint32_t)mbase + ((uint32_t)r - node * cl);
                            orow = out + ((size_t)node * N_COMP + m) * C_DIM
                                       + wc * 32;
                        }
                        #pragma unroll
                        for (int j = 0; j < 2; j++) {   // n8 pair (2j, 2j+1)
                            float ax = acc[mt][2*j][h*2],   ay = acc[mt][2*j][h*2+1];
                            float bx = acc[mt][2*j+1][h*2], by = acc[mt][2*j+1][h*2+1];
                            // even lanes send their block-b pair; odd send block-a
                            float sx = odd ? ax : bx;
                            float sy = odd ? ay : by;
                            float rx = __shfl_xor_sync(0xffffffffu, sx, 1);
                            float ry = __shfl_xor_sync(0xffffffffu, sy, 1);
                            float4 v;
                            int colofs;
                            if (!odd) {
                                v = make_float4(ax, ay, rx, ry);
                                colofs = (2*j) * 8 + qid * 2;
                            } else {
                                v = make_float4(rx, ry, bx, by);
                                colofs = (2*j + 1) * 8 + (qid - 1) * 2;
                            }
                            if (ok) *(float4*)(orow + colofs) = v;
                        }
                    }
                }
                if (++p == NBUF) p = 0;
            }
        }
    }
}

extern "C" void kernel_launch(void* const* d_in, const int* in_sizes, int n_in,
                              void* d_out, int out_size) {
    const float* x  = (const float*)d_in[0];
    const float* w  = (const float*)d_in[1];
    const float* pw = (const float*)d_in[2];
    float* out = (float*)d_out;

    const int n_nodes = in_sizes[0] / (N_COMP * C_DIM);

    int dev = 0, nsm = 148;
    cudaGetDevice(&dev);
    cudaDeviceGetAttribute(&nsm, cudaDevAttrMultiProcessorCount, dev);

    int t[4];
    int4 cum;
    for (int l = 0; l < 4; l++)
        t[l] = (n_nodes * (2 * l + 1) + BM - 1) / BM;
    cum.x = t[0];
    cum.y = cum.x + t[1];
    cum.z = cum.y + t[2];
    cum.w = cum.z + t[3];

    size_t smem_bytes = 196608;   // 192KB: 5x32KB X ring + 32KB W
    cudaFuncSetAttribute(tp_f16e,
                         cudaFuncAttributeMaxDynamicSharedMemorySize,
                         (int)smem_bytes);

    tp_f16e<<<nsm, THREADS, smem_bytes>>>(x, w, pw, out, n_nodes, cum);
}